// round 3
// baseline (speedup 1.0000x reference)
#include <cuda_runtime.h>
#include <math.h>

#define Db 256
#define NB 32
#define NTOK 4096
#define NS 8
#define HMLP 512
#define NBLK 4
#define ROWS (NB * NS)
#define EPS_LN 1e-3f
#define EPS_ATTN 1e-8f
#define ATT_SCALE 0.0625f

// ---------------- static scratch ----------------
__device__ float g_slots[ROWS * Db];
__device__ float g_sn[ROWS * Db];
__device__ float g_qk[ROWS * Db];
__device__ float g_qb[ROWS];
__device__ float g_partU[NB * NBLK * NS * Db];
__device__ float g_partZ[NB * NBLK * NS];
__device__ float g_u[ROWS * Db];
__device__ float g_gi[ROWS * 3 * Db];
__device__ float g_gh[ROWS * 3 * Db];
__device__ float g_hn[ROWS * Db];
__device__ float g_m1[ROWS * HMLP];
__device__ float g_Wqk[Db * Db];
__device__ float g_wcomb[3 * Db * Db];
__device__ float g_bcomb[3 * Db];
__device__ float g_wqbk[Db];
__device__ float g_bqk[Db];
__device__ float g_bqbk[1];

// ---------------- prep ----------------
__global__ void copy_slots_kernel(const float* __restrict__ slots) {
    int i = blockIdx.x * blockDim.x + threadIdx.x;
    g_slots[i] = slots[i];
}

// blk 0-2: bcomb = W_ih@bv + b_ih ; blk 3: wqbk = Wq^T bk, bqbk = bq.bk ; blk 4: bqk = bq @ Wk
__global__ void prep_micro_kernel(const float* __restrict__ W_ih, const float* __restrict__ b_ih,
                                  const float* __restrict__ bv, const float* __restrict__ Wq,
                                  const float* __restrict__ bq, const float* __restrict__ bk,
                                  const float* __restrict__ Wk) {
    int blk = blockIdx.x, t = threadIdx.x;
    if (blk < 3) {
        int o = blk * Db + t;
        float acc = b_ih[o];
        for (int d = 0; d < Db; d++) acc = fmaf(W_ih[o * Db + d], bv[d], acc);
        g_bcomb[o] = acc;
    } else if (blk == 3) {
        float acc = 0.f;
        for (int c = 0; c < Db; c++) acc = fmaf(Wq[c * Db + t], bk[c], acc);
        g_wqbk[t] = acc;
        __shared__ float red[Db];
        red[t] = bq[t] * bk[t];
        __syncthreads();
        for (int s = 128; s > 0; s >>= 1) {
            if (t < s) red[t] += red[t + s];
            __syncthreads();
        }
        if (t == 0) g_bqbk[0] = red[0];
    } else {
        float acc = 0.f;
        for (int c = 0; c < Db; c++) acc = fmaf(bq[c], Wk[c * Db + t], acc);
        g_bqk[t] = acc;
    }
}

// ---------------- tiled fp32 GEMM, 64x64 tile, 256 threads, 4x4 micro ----------------
// TRANSA: A is [K][R] row-major. TRANSB: B is [O][K] row-major (C=A@B^T), else B is [K][O].
template <int TRANSA, int TRANSB, int RELU>
__global__ void gemm_kernel(const float* __restrict__ A, const float* __restrict__ Bm,
                            const float* __restrict__ bias, const float* __restrict__ res,
                            float* __restrict__ C, int R, int O, int K) {
    __shared__ float As[16][68];
    __shared__ float Bs[16][68];
    const int r0 = blockIdx.x * 64;
    const int o0 = blockIdx.y * 64;
    const int tid = threadIdx.x;
    const int tx = tid & 15;
    const int ty = tid >> 4;
    float acc[4][4];
#pragma unroll
    for (int i = 0; i < 4; i++)
#pragma unroll
        for (int j = 0; j < 4; j++) acc[i][j] = 0.f;

    for (int kk = 0; kk < K; kk += 16) {
        if (TRANSA) {
            int k = tid >> 4;
            int r4 = (tid & 15) << 2;
            float4 v = *(const float4*)(A + (size_t)(kk + k) * R + r0 + r4);
            *(float4*)&As[k][r4] = v;
        } else {
            int r = tid >> 2;
            int k4 = (tid & 3) << 2;
            float4 v = *(const float4*)(A + (size_t)(r0 + r) * K + kk + k4);
            As[k4 + 0][r] = v.x; As[k4 + 1][r] = v.y; As[k4 + 2][r] = v.z; As[k4 + 3][r] = v.w;
        }
        if (TRANSB) {
            int o = tid >> 2;
            int k4 = (tid & 3) << 2;
            float4 v = *(const float4*)(Bm + (size_t)(o0 + o) * K + kk + k4);
            Bs[k4 + 0][o] = v.x; Bs[k4 + 1][o] = v.y; Bs[k4 + 2][o] = v.z; Bs[k4 + 3][o] = v.w;
        } else {
            int k = tid >> 4;
            int o4 = (tid & 15) << 2;
            float4 v = *(const float4*)(Bm + (size_t)(kk + k) * O + o0 + o4);
            *(float4*)&Bs[k][o4] = v;
        }
        __syncthreads();
#pragma unroll
        for (int k = 0; k < 16; k++) {
            float4 a4 = *(const float4*)&As[k][ty << 2];
            float4 b4 = *(const float4*)&Bs[k][tx << 2];
            float av[4] = {a4.x, a4.y, a4.z, a4.w};
            float bw[4] = {b4.x, b4.y, b4.z, b4.w};
#pragma unroll
            for (int i = 0; i < 4; i++)
#pragma unroll
                for (int j = 0; j < 4; j++) acc[i][j] = fmaf(av[i], bw[j], acc[i][j]);
        }
        __syncthreads();
    }
#pragma unroll
    for (int i = 0; i < 4; i++) {
        int r = r0 + (ty << 2) + i;
        float vv[4];
#pragma unroll
        for (int j = 0; j < 4; j++) {
            int o = o0 + (tx << 2) + j;
            float t = acc[i][j];
            if (bias) t += bias[o];
            if (RELU) t = fmaxf(t, 0.f);
            if (res) t += res[(size_t)r * O + o];
            vv[j] = t;
        }
        float4 v;
        v.x = vv[0]; v.y = vv[1]; v.z = vv[2]; v.w = vv[3];
        *(float4*)(C + (size_t)r * O + o0 + (tx << 2)) = v;
    }
}

// ---------------- slot LN + qb ----------------
__global__ void slot_ln_kernel(const float* __restrict__ g, const float* __restrict__ b) {
    int row = blockIdx.x;
    int t = threadIdx.x;
    int w = t >> 5, l = t & 31;
    float x = g_slots[row * Db + t];
    __shared__ float sm[8], sm2[8], bc[2];
    float s = x, s2 = x * x;
#pragma unroll
    for (int o = 16; o; o >>= 1) {
        s += __shfl_xor_sync(0xffffffffu, s, o);
        s2 += __shfl_xor_sync(0xffffffffu, s2, o);
    }
    if (l == 0) { sm[w] = s; sm2[w] = s2; }
    __syncthreads();
    if (t == 0) {
        float a = 0.f, a2 = 0.f;
#pragma unroll
        for (int i = 0; i < 8; i++) { a += sm[i]; a2 += sm2[i]; }
        float m = a * (1.f / Db);
        bc[0] = m;
        bc[1] = rsqrtf(a2 * (1.f / Db) - m * m + EPS_LN);
    }
    __syncthreads();
    float sn = (x - bc[0]) * bc[1] * g[t] + b[t];
    g_sn[row * Db + t] = sn;
    float p = sn * g_wqbk[t];
#pragma unroll
    for (int o = 16; o; o >>= 1) p += __shfl_xor_sync(0xffffffffu, p, o);
    __syncthreads();
    if (l == 0) sm[w] = p;
    __syncthreads();
    if (t == 0) {
        float acc = g_bqbk[0];
#pragma unroll
        for (int i = 0; i < 8; i++) acc += sm[i];
        g_qb[row] = acc;
    }
}

// ---------------- main fused pass ----------------
__global__ void __launch_bounds__(256, 1)
main_pass_kernel(const float* __restrict__ inputs, const float* __restrict__ ln_g,
                 const float* __restrict__ ln_b, int reverse) {
    const int batch = blockIdx.x / NBLK;
    const int chunk = blockIdx.x % NBLK;
    const int tid = threadIdx.x;
    const int w = tid >> 5, l = tid & 31;

    float qk[NS][8];
    {
        const float4* qkb = (const float4*)&g_qk[batch * NS * Db];
#pragma unroll
        for (int i = 0; i < NS; i++) {
            float4 a = qkb[i * 64 + l * 2];
            float4 c = qkb[i * 64 + l * 2 + 1];
            qk[i][0] = a.x; qk[i][1] = a.y; qk[i][2] = a.z; qk[i][3] = a.w;
            qk[i][4] = c.x; qk[i][5] = c.y; qk[i][6] = c.z; qk[i][7] = c.w;
        }
    }
    float gg[8], bb[8];
    {
        float4 a = ((const float4*)ln_g)[l * 2];
        float4 c = ((const float4*)ln_g)[l * 2 + 1];
        gg[0] = a.x; gg[1] = a.y; gg[2] = a.z; gg[3] = a.w;
        gg[4] = c.x; gg[5] = c.y; gg[6] = c.z; gg[7] = c.w;
        float4 d = ((const float4*)ln_b)[l * 2];
        float4 e = ((const float4*)ln_b)[l * 2 + 1];
        bb[0] = d.x; bb[1] = d.y; bb[2] = d.z; bb[3] = d.w;
        bb[4] = e.x; bb[5] = e.y; bb[6] = e.z; bb[7] = e.w;
    }
    float qb[NS];
#pragma unroll
    for (int i = 0; i < NS; i++) qb[i] = g_qb[batch * NS + i];

    float U[NS][8];
    float Z[NS];
#pragma unroll
    for (int i = 0; i < NS; i++) {
        Z[i] = 0.f;
#pragma unroll
        for (int k = 0; k < 8; k++) U[i][k] = 0.f;
    }

    const int TPW = NTOK / NBLK / 8;  // 128 tokens per warp
    const int base = chunk * (NTOK / NBLK) + w * TPW;

    int tok0 = reverse ? (base + TPW - 1) : base;
    const float4* xr = (const float4*)&inputs[(size_t)(batch * NTOK + tok0) * Db];
    float4 xa = xr[l * 2], xc = xr[l * 2 + 1];

    for (int tt = 0; tt < TPW; tt++) {
        float x[8] = {xa.x, xa.y, xa.z, xa.w, xc.x, xc.y, xc.z, xc.w};
        if (tt + 1 < TPW) {
            int tok = reverse ? (base + TPW - 2 - tt) : (base + tt + 1);
            const float4* nx = (const float4*)&inputs[(size_t)(batch * NTOK + tok) * Db];
            xa = nx[l * 2];
            xc = nx[l * 2 + 1];
        }
        float s = 0.f, s2 = 0.f;
#pragma unroll
        for (int k = 0; k < 8; k++) {
            s += x[k];
            s2 = fmaf(x[k], x[k], s2);
        }
#pragma unroll
        for (int o = 16; o; o >>= 1) {
            s += __shfl_xor_sync(0xffffffffu, s, o);
            s2 += __shfl_xor_sync(0xffffffffu, s2, o);
        }
        float mean = s * (1.f / Db);
        float rstd = rsqrtf(s2 * (1.f / Db) - mean * mean + EPS_LN);
        float xn[8];
#pragma unroll
        for (int k = 0; k < 8; k++) xn[k] = (x[k] - mean) * rstd * gg[k] + bb[k];
        float d[NS];
#pragma unroll
        for (int i = 0; i < NS; i++) {
            float a = 0.f;
#pragma unroll
            for (int k = 0; k < 8; k++) a = fmaf(qk[i][k], xn[k], a);
            d[i] = a;
        }
#pragma unroll
        for (int o = 16; o; o >>= 1) {
#pragma unroll
            for (int i = 0; i < NS; i++) d[i] += __shfl_xor_sync(0xffffffffu, d[i], o);
        }
        float mx = -1e30f;
#pragma unroll
        for (int i = 0; i < NS; i++) {
            d[i] = fmaf(d[i] + qb[i], ATT_SCALE, 0.f);
            mx = fmaxf(mx, d[i]);
        }
        float p[NS], se = 0.f;
#pragma unroll
        for (int i = 0; i < NS; i++) {
            p[i] = __expf(d[i] - mx);
            se += p[i];
        }
        float inv = 1.f / se;
#pragma unroll
        for (int i = 0; i < NS; i++) {
            p[i] = fmaf(p[i], inv, EPS_ATTN);
            Z[i] += p[i];
#pragma unroll
            for (int k = 0; k < 8; k++) U[i][k] = fmaf(p[i], xn[k], U[i][k]);
        }
    }

    // serial cross-warp reduction in shared memory (deterministic)
    __shared__ float sU[NS * Db];
    __shared__ float sZ[NS];
    for (int ww = 0; ww < 8; ww++) {
        if (w == ww) {
#pragma unroll
            for (int i = 0; i < NS; i++) {
#pragma unroll
                for (int k = 0; k < 8; k++) {
                    int idx = i * Db + l * 8 + k;
                    if (ww == 0) sU[idx] = U[i][k];
                    else sU[idx] += U[i][k];
                }
            }
            if (l == 0) {
#pragma unroll
                for (int i = 0; i < NS; i++) {
                    if (ww == 0) sZ[i] = Z[i];
                    else sZ[i] += Z[i];
                }
            }
        }
        __syncthreads();
    }
    int outb = (batch * NBLK + chunk) * NS * Db;
    for (int idx = tid; idx < NS * Db; idx += 256) g_partU[outb + idx] = sU[idx];
    if (tid < NS) g_partZ[(batch * NBLK + chunk) * NS + tid] = sZ[tid];
}

// ---------------- finalize: u = sum(partU)/sum(partZ) ----------------
__global__ void finalize_kernel() {
    int row = blockIdx.x;
    int t = threadIdx.x;
    int b = row >> 3, i = row & 7;
    float Z = 0.f, s = 0.f;
#pragma unroll
    for (int c = 0; c < NBLK; c++) {
        Z += g_partZ[(b * NBLK + c) * NS + i];
        s += g_partU[((b * NBLK + c) * NS + i) * Db + t];
    }
    g_u[row * Db + t] = s / Z;
}

// ---------------- GRU elementwise + LN(mlp) fused ----------------
__global__ void gru_ln_kernel(const float* __restrict__ g, const float* __restrict__ bpar) {
    int row = blockIdx.x;
    int t = threadIdx.x;
    int w = t >> 5, l = t & 31;
    const float* gi = &g_gi[row * 3 * Db];
    const float* gh = &g_gh[row * 3 * Db];
    float h = g_slots[row * Db + t];
    float r = 1.f / (1.f + expf(-(gi[t] + gh[t])));
    float z = 1.f / (1.f + expf(-(gi[Db + t] + gh[Db + t])));
    float n = tanhf(gi[2 * Db + t] + r * gh[2 * Db + t]);
    float hn = (1.f - z) * n + z * h;
    g_slots[row * Db + t] = hn;
    // LN
    __shared__ float sm[8], sm2[8], bc[2];
    float s = hn, s2 = hn * hn;
#pragma unroll
    for (int o = 16; o; o >>= 1) {
        s += __shfl_xor_sync(0xffffffffu, s, o);
        s2 += __shfl_xor_sync(0xffffffffu, s2, o);
    }
    if (l == 0) { sm[w] = s; sm2[w] = s2; }
    __syncthreads();
    if (t == 0) {
        float a = 0.f, a2 = 0.f;
#pragma unroll
        for (int i = 0; i < 8; i++) { a += sm[i]; a2 += sm2[i]; }
        float m = a * (1.f / Db);
        bc[0] = m;
        bc[1] = rsqrtf(a2 * (1.f / Db) - m * m + EPS_LN);
    }
    __syncthreads();
    g_hn[row * Db + t] = (hn - bc[0]) * bc[1] * g[t] + bpar[t];
}

// ---------------- launch ----------------
extern "C" void kernel_launch(void* const* d_in, const int* in_sizes, int n_in,
                              void* d_out, int out_size) {
    const float* inputs = (const float*)d_in[0];
    const float* slots = (const float*)d_in[1];
    const float* ln_in_g = (const float*)d_in[3];
    const float* ln_in_b = (const float*)d_in[4];
    const float* ln_slot_g = (const float*)d_in[5];
    const float* ln_slot_b = (const float*)d_in[6];
    const float* ln_mlp_g = (const float*)d_in[7];
    const float* ln_mlp_b = (const float*)d_in[8];
    const float* Wq = (const float*)d_in[9];
    const float* bq = (const float*)d_in[10];
    const float* Wk = (const float*)d_in[11];
    const float* bk = (const float*)d_in[12];
    const float* Wv = (const float*)d_in[13];
    const float* bv = (const float*)d_in[14];
    const float* W_ih = (const float*)d_in[15];
    const float* b_ih = (const float*)d_in[16];
    const float* W_hh = (const float*)d_in[17];
    const float* b_hh = (const float*)d_in[18];
    const float* W1 = (const float*)d_in[19];
    const float* b1 = (const float*)d_in[20];
    const float* W2 = (const float*)d_in[21];
    const float* b2 = (const float*)d_in[22];
    float* out = (float*)d_out;

    float *p_sn, *p_qk, *p_u, *p_gi, *p_gh, *p_hn, *p_m1, *p_slots;
    float *p_Wqk, *p_wcomb, *p_bcomb, *p_bqk;
    cudaGetSymbolAddress((void**)&p_sn, g_sn);
    cudaGetSymbolAddress((void**)&p_qk, g_qk);
    cudaGetSymbolAddress((void**)&p_u, g_u);
    cudaGetSymbolAddress((void**)&p_gi, g_gi);
    cudaGetSymbolAddress((void**)&p_gh, g_gh);
    cudaGetSymbolAddress((void**)&p_hn, g_hn);
    cudaGetSymbolAddress((void**)&p_m1, g_m1);
    cudaGetSymbolAddress((void**)&p_slots, g_slots);
    cudaGetSymbolAddress((void**)&p_Wqk, g_Wqk);
    cudaGetSymbolAddress((void**)&p_wcomb, g_wcomb);
    cudaGetSymbolAddress((void**)&p_bcomb, g_bcomb);
    cudaGetSymbolAddress((void**)&p_bqk, g_bqk);

    // prep
    copy_slots_kernel<<<ROWS * Db / 256, 256>>>(slots);
    prep_micro_kernel<<<5, 256>>>(W_ih, b_ih, bv, Wq, bq, bk, Wk);
    // Wqk = Wq^T @ Wk  [256,256]
    gemm_kernel<1, 0, 0><<<dim3(4, 4), 256>>>(Wq, Wk, nullptr, nullptr, p_Wqk, 256, 256, 256);
    // wcomb = W_ih @ Wv  [768,256]
    gemm_kernel<0, 0, 0><<<dim3(12, 4), 256>>>(W_ih, Wv, nullptr, nullptr, p_wcomb, 768, 256, 256);

    for (int it = 0; it < 3; it++) {
        slot_ln_kernel<<<ROWS, 256>>>(ln_slot_g, ln_slot_b);
        // qk = sn @ Wqk + bqk
        gemm_kernel<0, 0, 0><<<dim3(4, 4), 256>>>(p_sn, p_Wqk, p_bqk, nullptr, p_qk, 256, 256, 256);
        main_pass_kernel<<<NB * NBLK, 256>>>(inputs, ln_in_g, ln_in_b, it & 1);
        finalize_kernel<<<ROWS, 256>>>();
        // gi = u @ wcomb^T + bcomb  [256,768]
        gemm_kernel<0, 1, 0><<<dim3(4, 12), 256>>>(p_u, p_wcomb, p_bcomb, nullptr, p_gi, 256, 768, 256);
        // gh = slots @ W_hh^T + b_hh  [256,768]
        gemm_kernel<0, 1, 0><<<dim3(4, 12), 256>>>(p_slots, W_hh, b_hh, nullptr, p_gh, 256, 768, 256);
        gru_ln_kernel<<<ROWS, 256>>>(ln_mlp_g, ln_mlp_b);
        // m1 = relu(hn @ W1^T + b1)  [256,512]
        gemm_kernel<0, 1, 1><<<dim3(4, 8), 256>>>(p_hn, W1, b1, nullptr, p_m1, 256, 512, 256);
        // slots = m1 @ W2^T + b2 + slots  [256,256] (last iter writes d_out)
        float* Cdst = (it == 2) ? out : p_slots;
        gemm_kernel<0, 1, 0><<<dim3(4, 4), 256>>>(p_m1, W2, b2, p_slots, Cdst, 256, 256, 512);
    }
}

// round 5
// speedup vs baseline: 1.0741x; 1.0741x over previous
#include <cuda_runtime.h>
#include <math.h>

#define Db 256
#define NB 32
#define NTOK 4096
#define NS 8
#define HMLP 512
#define NBLK 4
#define ROWS (NB * NS)
#define EPS_LN 1e-3f
#define EPS_ATTN 1e-8f
#define ATT_SCALE 0.0625f

// ---------------- static scratch ----------------
__device__ float g_slots[ROWS * Db];
__device__ float g_qk[ROWS * Db];
__device__ float g_qb[ROWS];
__device__ float g_partU[NB * NBLK * NS * Db];
__device__ float g_partZ[NB * NBLK * NS];
__device__ float g_gi[ROWS * 3 * Db];
__device__ float g_gh[ROWS * 3 * Db];
__device__ float g_hn[ROWS * Db];
__device__ float g_m1[ROWS * HMLP];
__device__ float g_Wqk[Db * Db];
__device__ float g_wcomb[3 * Db * Db];
__device__ float g_bcomb[3 * Db];
__device__ float g_wqbk[Db];
__device__ float g_bqk[Db];
__device__ float g_bqbk[1];

// ---------------- prep ----------------
__global__ void copy_slots_kernel(const float* __restrict__ slots) {
    int i = blockIdx.x * blockDim.x + threadIdx.x;
    g_slots[i] = slots[i];
}

// blk 0-2: bcomb = W_ih@bv + b_ih ; blk 3: wqbk = Wq^T bk, bqbk = bq.bk ; blk 4: bqk = bq @ Wk
__global__ void prep_micro_kernel(const float* __restrict__ W_ih, const float* __restrict__ b_ih,
                                  const float* __restrict__ bv, const float* __restrict__ Wq,
                                  const float* __restrict__ bq, const float* __restrict__ bk,
                                  const float* __restrict__ Wk) {
    int blk = blockIdx.x, t = threadIdx.x;
    if (blk < 3) {
        int o = blk * Db + t;
        float acc = b_ih[o];
        for (int d = 0; d < Db; d++) acc = fmaf(W_ih[o * Db + d], bv[d], acc);
        g_bcomb[o] = acc;
    } else if (blk == 3) {
        float acc = 0.f;
        for (int c = 0; c < Db; c++) acc = fmaf(Wq[c * Db + t], bk[c], acc);
        g_wqbk[t] = acc;
        __shared__ float red[Db];
        red[t] = bq[t] * bk[t];
        __syncthreads();
        for (int s = 128; s > 0; s >>= 1) {
            if (t < s) red[t] += red[t + s];
            __syncthreads();
        }
        if (t == 0) g_bqbk[0] = red[0];
    } else {
        float acc = 0.f;
        for (int c = 0; c < Db; c++) acc = fmaf(bq[c], Wk[c * Db + t], acc);
        g_bqk[t] = acc;
    }
}

// ---------------- GEMM v2: 32x64 tile, K-step 32, 256 threads, 2x4 micro ----------------
// TRANSA: A is [K][R] row-major. TRANSB: B is [O][K] row-major (C=A@B^T), else B is [K][O].
// NOTE: Bs row stride MUST be a multiple of 4 floats (16B) for the float4 reads.
template <int TRANSA, int TRANSB, int RELU>
__global__ void gemm2_kernel(const float* __restrict__ A, const float* __restrict__ Bm,
                             const float* __restrict__ bias, const float* __restrict__ res,
                             float* __restrict__ C, int R, int O, int K) {
    __shared__ float As[32][33];
    __shared__ float Bs[32][68];
    const int r0 = blockIdx.x * 32;
    const int o0 = blockIdx.y * 64;
    const int tid = threadIdx.x;
    const int tx = tid & 15;
    const int ty = tid >> 4;
    float acc[2][4];
#pragma unroll
    for (int i = 0; i < 2; i++)
#pragma unroll
        for (int j = 0; j < 4; j++) acc[i][j] = 0.f;

    for (int kk = 0; kk < K; kk += 32) {
        if (TRANSA) {
            int k = tid >> 3;
            int r4 = (tid & 7) << 2;
            float4 v = *(const float4*)(A + (size_t)(kk + k) * R + r0 + r4);
            As[k][r4 + 0] = v.x; As[k][r4 + 1] = v.y; As[k][r4 + 2] = v.z; As[k][r4 + 3] = v.w;
        } else {
            int r = tid >> 3;
            int k4 = (tid & 7) << 2;
            float4 v = *(const float4*)(A + (size_t)(r0 + r) * K + kk + k4);
            As[k4 + 0][r] = v.x; As[k4 + 1][r] = v.y; As[k4 + 2][r] = v.z; As[k4 + 3][r] = v.w;
        }
        if (TRANSB) {
            int o = tid >> 2;
            int k4 = (tid & 3) << 3;
#pragma unroll
            for (int j = 0; j < 2; j++) {
                float4 v = *(const float4*)(Bm + (size_t)(o0 + o) * K + kk + k4 + j * 4);
                Bs[k4 + j * 4 + 0][o] = v.x; Bs[k4 + j * 4 + 1][o] = v.y;
                Bs[k4 + j * 4 + 2][o] = v.z; Bs[k4 + j * 4 + 3][o] = v.w;
            }
        } else {
            int k = tid >> 3;
            int o8 = (tid & 7) << 3;
#pragma unroll
            for (int j = 0; j < 2; j++) {
                float4 v = *(const float4*)(Bm + (size_t)(kk + k) * O + o0 + o8 + j * 4);
                *(float4*)&Bs[k][o8 + j * 4] = v;
            }
        }
        __syncthreads();
#pragma unroll
        for (int k = 0; k < 32; k++) {
            float a0 = As[k][ty * 2 + 0];
            float a1 = As[k][ty * 2 + 1];
            float4 b4 = *(const float4*)&Bs[k][tx << 2];
            acc[0][0] = fmaf(a0, b4.x, acc[0][0]); acc[0][1] = fmaf(a0, b4.y, acc[0][1]);
            acc[0][2] = fmaf(a0, b4.z, acc[0][2]); acc[0][3] = fmaf(a0, b4.w, acc[0][3]);
            acc[1][0] = fmaf(a1, b4.x, acc[1][0]); acc[1][1] = fmaf(a1, b4.y, acc[1][1]);
            acc[1][2] = fmaf(a1, b4.z, acc[1][2]); acc[1][3] = fmaf(a1, b4.w, acc[1][3]);
        }
        __syncthreads();
    }
#pragma unroll
    for (int i = 0; i < 2; i++) {
        int r = r0 + ty * 2 + i;
        float vv[4];
#pragma unroll
        for (int j = 0; j < 4; j++) {
            int o = o0 + (tx << 2) + j;
            float t = acc[i][j];
            if (bias) t += bias[o];
            if (RELU) t = fmaxf(t, 0.f);
            if (res) t += res[(size_t)r * O + o];
            vv[j] = t;
        }
        float4 v;
        v.x = vv[0]; v.y = vv[1]; v.z = vv[2]; v.w = vv[3];
        *(float4*)(C + (size_t)r * O + o0 + (tx << 2)) = v;
    }
}

// ---------------- fused slot LN + qb + qk GEMM (one block per batch) ----------------
__global__ void __launch_bounds__(256)
lnqk_kernel(const float* __restrict__ gpar, const float* __restrict__ bpar) {
    const int b = blockIdx.x;
    const int t = threadIdx.x;
    const int w = t >> 5, l = t & 31;
    __shared__ float sn[NS][Db];
    __shared__ float qbs[NS];

    // warp w handles slot row w
    const float4* sr = (const float4*)&g_slots[(b * NS + w) * Db];
    float4 a = sr[l * 2], c = sr[l * 2 + 1];
    float x[8] = {a.x, a.y, a.z, a.w, c.x, c.y, c.z, c.w};
    float s = 0.f, s2 = 0.f;
#pragma unroll
    for (int k = 0; k < 8; k++) {
        s += x[k];
        s2 = fmaf(x[k], x[k], s2);
    }
#pragma unroll
    for (int o = 16; o; o >>= 1) {
        s += __shfl_xor_sync(0xffffffffu, s, o);
        s2 += __shfl_xor_sync(0xffffffffu, s2, o);
    }
    float mean = s * (1.f / Db);
    float rstd = rsqrtf(s2 * (1.f / Db) - mean * mean + EPS_LN);
    float4 ga = ((const float4*)gpar)[l * 2], gc = ((const float4*)gpar)[l * 2 + 1];
    float4 ba = ((const float4*)bpar)[l * 2], bc = ((const float4*)bpar)[l * 2 + 1];
    float gg[8] = {ga.x, ga.y, ga.z, ga.w, gc.x, gc.y, gc.z, gc.w};
    float bb[8] = {ba.x, ba.y, ba.z, ba.w, bc.x, bc.y, bc.z, bc.w};
    float4 wa = ((const float4*)g_wqbk)[l * 2], wc = ((const float4*)g_wqbk)[l * 2 + 1];
    float wq[8] = {wa.x, wa.y, wa.z, wa.w, wc.x, wc.y, wc.z, wc.w};
    float p = 0.f;
#pragma unroll
    for (int k = 0; k < 8; k++) {
        float v = (x[k] - mean) * rstd * gg[k] + bb[k];
        sn[w][l * 8 + k] = v;
        p = fmaf(v, wq[k], p);
    }
#pragma unroll
    for (int o = 16; o; o >>= 1) p += __shfl_xor_sync(0xffffffffu, p, o);
    if (l == 0) qbs[w] = p + g_bqbk[0];
    __syncthreads();
    if (t < NS) g_qb[b * NS + t] = qbs[t];

    // qk[i][t] = sum_k sn[i][k] * Wqk[k][t] + bqk[t]
    float acc[NS];
#pragma unroll
    for (int i = 0; i < NS; i++) acc[i] = g_bqk[t];
    for (int k = 0; k < Db; k += 4) {
        float w0 = g_Wqk[(k + 0) * Db + t];
        float w1 = g_Wqk[(k + 1) * Db + t];
        float w2 = g_Wqk[(k + 2) * Db + t];
        float w3 = g_Wqk[(k + 3) * Db + t];
#pragma unroll
        for (int i = 0; i < NS; i++) {
            float4 s4 = *(const float4*)&sn[i][k];
            acc[i] = fmaf(s4.x, w0, acc[i]);
            acc[i] = fmaf(s4.y, w1, acc[i]);
            acc[i] = fmaf(s4.z, w2, acc[i]);
            acc[i] = fmaf(s4.w, w3, acc[i]);
        }
    }
#pragma unroll
    for (int i = 0; i < NS; i++) g_qk[(b * NS + i) * Db + t] = acc[i];
}

// ---------------- main fused pass ----------------
__global__ void __launch_bounds__(256, 1)
main_pass_kernel(const float* __restrict__ inputs, const float* __restrict__ ln_g,
                 const float* __restrict__ ln_b, int reverse) {
    const int batch = blockIdx.x / NBLK;
    const int chunk = blockIdx.x % NBLK;
    const int tid = threadIdx.x;
    const int w = tid >> 5, l = tid & 31;

    float qk[NS][8];
    {
        const float4* qkb = (const float4*)&g_qk[batch * NS * Db];
#pragma unroll
        for (int i = 0; i < NS; i++) {
            float4 a = qkb[i * 64 + l * 2];
            float4 c = qkb[i * 64 + l * 2 + 1];
            qk[i][0] = a.x; qk[i][1] = a.y; qk[i][2] = a.z; qk[i][3] = a.w;
            qk[i][4] = c.x; qk[i][5] = c.y; qk[i][6] = c.z; qk[i][7] = c.w;
        }
    }
    float gg[8], bb[8];
    {
        float4 a = ((const float4*)ln_g)[l * 2];
        float4 c = ((const float4*)ln_g)[l * 2 + 1];
        gg[0] = a.x; gg[1] = a.y; gg[2] = a.z; gg[3] = a.w;
        gg[4] = c.x; gg[5] = c.y; gg[6] = c.z; gg[7] = c.w;
        float4 d = ((const float4*)ln_b)[l * 2];
        float4 e = ((const float4*)ln_b)[l * 2 + 1];
        bb[0] = d.x; bb[1] = d.y; bb[2] = d.z; bb[3] = d.w;
        bb[4] = e.x; bb[5] = e.y; bb[6] = e.z; bb[7] = e.w;
    }
    float qb[NS];
#pragma unroll
    for (int i = 0; i < NS; i++) qb[i] = g_qb[batch * NS + i];

    float U[NS][8];
    float Z[NS];
#pragma unroll
    for (int i = 0; i < NS; i++) {
        Z[i] = 0.f;
#pragma unroll
        for (int k = 0; k < 8; k++) U[i][k] = 0.f;
    }

    const int TPW = NTOK / NBLK / 8;  // 128 tokens per warp
    const int base = chunk * (NTOK / NBLK) + w * TPW;

    int tok0 = reverse ? (base + TPW - 1) : base;
    const float4* xr = (const float4*)&inputs[(size_t)(batch * NTOK + tok0) * Db];
    float4 xa = xr[l * 2], xc = xr[l * 2 + 1];

    for (int tt = 0; tt < TPW; tt++) {
        float x[8] = {xa.x, xa.y, xa.z, xa.w, xc.x, xc.y, xc.z, xc.w};
        if (tt + 1 < TPW) {
            int tok = reverse ? (base + TPW - 2 - tt) : (base + tt + 1);
            const float4* nx = (const float4*)&inputs[(size_t)(batch * NTOK + tok) * Db];
            xa = nx[l * 2];
            xc = nx[l * 2 + 1];
        }
        float s = 0.f, s2 = 0.f;
#pragma unroll
        for (int k = 0; k < 8; k++) {
            s += x[k];
            s2 = fmaf(x[k], x[k], s2);
        }
#pragma unroll
        for (int o = 16; o; o >>= 1) {
            s += __shfl_xor_sync(0xffffffffu, s, o);
            s2 += __shfl_xor_sync(0xffffffffu, s2, o);
        }
        float mean = s * (1.f / Db);
        float rstd = rsqrtf(s2 * (1.f / Db) - mean * mean + EPS_LN);
        float xn[8];
#pragma unroll
        for (int k = 0; k < 8; k++) xn[k] = (x[k] - mean) * rstd * gg[k] + bb[k];
        float d[NS];
#pragma unroll
        for (int i = 0; i < NS; i++) {
            float a = 0.f;
#pragma unroll
            for (int k = 0; k < 8; k++) a = fmaf(qk[i][k], xn[k], a);
            d[i] = a;
        }
#pragma unroll
        for (int o = 16; o; o >>= 1) {
#pragma unroll
            for (int i = 0; i < NS; i++) d[i] += __shfl_xor_sync(0xffffffffu, d[i], o);
        }
        float mx = -1e30f;
#pragma unroll
        for (int i = 0; i < NS; i++) {
            d[i] = fmaf(d[i] + qb[i], ATT_SCALE, 0.f);
            mx = fmaxf(mx, d[i]);
        }
        float p[NS], se = 0.f;
#pragma unroll
        for (int i = 0; i < NS; i++) {
            p[i] = __expf(d[i] - mx);
            se += p[i];
        }
        float inv = 1.f / se;
#pragma unroll
        for (int i = 0; i < NS; i++) {
            p[i] = fmaf(p[i], inv, EPS_ATTN);
            Z[i] += p[i];
#pragma unroll
            for (int k = 0; k < 8; k++) U[i][k] = fmaf(p[i], xn[k], U[i][k]);
        }
    }

    __shared__ float sU[NS * Db];
    __shared__ float sZ[NS];
    for (int ww = 0; ww < 8; ww++) {
        if (w == ww) {
#pragma unroll
            for (int i = 0; i < NS; i++) {
#pragma unroll
                for (int k = 0; k < 8; k++) {
                    int idx = i * Db + l * 8 + k;
                    if (ww == 0) sU[idx] = U[i][k];
                    else sU[idx] += U[i][k];
                }
            }
            if (l == 0) {
#pragma unroll
                for (int i = 0; i < NS; i++) {
                    if (ww == 0) sZ[i] = Z[i];
                    else sZ[i] += Z[i];
                }
            }
        }
        __syncthreads();
    }
    int outb = (batch * NBLK + chunk) * NS * Db;
    for (int idx = tid; idx < NS * Db; idx += 256) g_partU[outb + idx] = sU[idx];
    if (tid < NS) g_partZ[(batch * NBLK + chunk) * NS + tid] = sZ[tid];
}

// ---------------- fused finalize + gi/gh GEMM ----------------
// z=0: A = u = (sum_c partU)/(sum_c partZ), B = wcomb (TRANSB), bias bcomb -> g_gi
// z=1: A = g_slots, B = W_hh (TRANSB), bias b_hh -> g_gh
__global__ void __launch_bounds__(256)
gigh_kernel(const float* __restrict__ W_hh, const float* __restrict__ b_hh) {
    const int z = blockIdx.z;
    const int r0 = blockIdx.x * 32;
    const int o0 = blockIdx.y * 64;
    const int tid = threadIdx.x;
    const int tx = tid & 15;
    const int ty = tid >> 4;
    __shared__ float As[32][33];
    __shared__ float Bs[32][68];
    __shared__ float invZ[32];

    if (z == 0 && tid < 32) {
        int r = r0 + tid, bi = r >> 3, si = r & 7;
        float zz = 0.f;
#pragma unroll
        for (int c = 0; c < NBLK; c++) zz += g_partZ[(bi * NBLK + c) * NS + si];
        invZ[tid] = 1.f / zz;
    }
    __syncthreads();

    const float* Bsrc = z ? W_hh : g_wcomb;
    const float* bias = z ? b_hh : g_bcomb;
    float* Cout = z ? g_gh : g_gi;

    float acc[2][4];
#pragma unroll
    for (int i = 0; i < 2; i++)
#pragma unroll
        for (int j = 0; j < 4; j++) acc[i][j] = 0.f;

    for (int kk = 0; kk < Db; kk += 32) {
        {
            int r = tid >> 3;
            int k4 = (tid & 7) << 2;
            float4 v;
            if (z == 0) {
                int gr = r0 + r, bi = gr >> 3, si = gr & 7;
                float4 s = *(const float4*)&g_partU[((bi * NBLK + 0) * NS + si) * Db + kk + k4];
#pragma unroll
                for (int c = 1; c < NBLK; c++) {
                    float4 vv = *(const float4*)&g_partU[((bi * NBLK + c) * NS + si) * Db + kk + k4];
                    s.x += vv.x; s.y += vv.y; s.z += vv.z; s.w += vv.w;
                }
                float iz = invZ[r];
                v.x = s.x * iz; v.y = s.y * iz; v.z = s.z * iz; v.w = s.w * iz;
            } else {
                v = *(const float4*)&g_slots[(r0 + r) * Db + kk + k4];
            }
            As[k4 + 0][r] = v.x; As[k4 + 1][r] = v.y; As[k4 + 2][r] = v.z; As[k4 + 3][r] = v.w;
        }
        {
            int o = tid >> 2;
            int k4 = (tid & 3) << 3;
#pragma unroll
            for (int j = 0; j < 2; j++) {
                float4 v = *(const float4*)(Bsrc + (size_t)(o0 + o) * Db + kk + k4 + j * 4);
                Bs[k4 + j * 4 + 0][o] = v.x; Bs[k4 + j * 4 + 1][o] = v.y;
                Bs[k4 + j * 4 + 2][o] = v.z; Bs[k4 + j * 4 + 3][o] = v.w;
            }
        }
        __syncthreads();
#pragma unroll
        for (int k = 0; k < 32; k++) {
            float a0 = As[k][ty * 2 + 0];
            float a1 = As[k][ty * 2 + 1];
            float4 b4 = *(const float4*)&Bs[k][tx << 2];
            acc[0][0] = fmaf(a0, b4.x, acc[0][0]); acc[0][1] = fmaf(a0, b4.y, acc[0][1]);
            acc[0][2] = fmaf(a0, b4.z, acc[0][2]); acc[0][3] = fmaf(a0, b4.w, acc[0][3]);
            acc[1][0] = fmaf(a1, b4.x, acc[1][0]); acc[1][1] = fmaf(a1, b4.y, acc[1][1]);
            acc[1][2] = fmaf(a1, b4.z, acc[1][2]); acc[1][3] = fmaf(a1, b4.w, acc[1][3]);
        }
        __syncthreads();
    }
#pragma unroll
    for (int i = 0; i < 2; i++) {
        int r = r0 + ty * 2 + i;
        float4 v;
        v.x = acc[i][0] + bias[o0 + (tx << 2) + 0];
        v.y = acc[i][1] + bias[o0 + (tx << 2) + 1];
        v.z = acc[i][2] + bias[o0 + (tx << 2) + 2];
        v.w = acc[i][3] + bias[o0 + (tx << 2) + 3];
        *(float4*)(Cout + (size_t)r * (3 * Db) + o0 + (tx << 2)) = v;
    }
}

// ---------------- GRU elementwise + LN(mlp) fused ----------------
__global__ void gru_ln_kernel(const float* __restrict__ g, const float* __restrict__ bpar) {
    int row = blockIdx.x;
    int t = threadIdx.x;
    int w = t >> 5, l = t & 31;
    const float* gi = &g_gi[row * 3 * Db];
    const float* gh = &g_gh[row * 3 * Db];
    float h = g_slots[row * Db + t];
    float r = 1.f / (1.f + expf(-(gi[t] + gh[t])));
    float z = 1.f / (1.f + expf(-(gi[Db + t] + gh[Db + t])));
    float n = tanhf(gi[2 * Db + t] + r * gh[2 * Db + t]);
    float hn = (1.f - z) * n + z * h;
    g_slots[row * Db + t] = hn;
    __shared__ float sm[8], sm2[8], bc[2];
    float s = hn, s2 = hn * hn;
#pragma unroll
    for (int o = 16; o; o >>= 1) {
        s += __shfl_xor_sync(0xffffffffu, s, o);
        s2 += __shfl_xor_sync(0xffffffffu, s2, o);
    }
    if (l == 0) { sm[w] = s; sm2[w] = s2; }
    __syncthreads();
    if (t == 0) {
        float a = 0.f, a2 = 0.f;
#pragma unroll
        for (int i = 0; i < 8; i++) { a += sm[i]; a2 += sm2[i]; }
        float m = a * (1.f / Db);
        bc[0] = m;
        bc[1] = rsqrtf(a2 * (1.f / Db) - m * m + EPS_LN);
    }
    __syncthreads();
    g_hn[row * Db + t] = (hn - bc[0]) * bc[1] * g[t] + bpar[t];
}

// ---------------- launch ----------------
extern "C" void kernel_launch(void* const* d_in, const int* in_sizes, int n_in,
                              void* d_out, int out_size) {
    const float* inputs = (const float*)d_in[0];
    const float* slots = (const float*)d_in[1];
    const float* ln_in_g = (const float*)d_in[3];
    const float* ln_in_b = (const float*)d_in[4];
    const float* ln_slot_g = (const float*)d_in[5];
    const float* ln_slot_b = (const float*)d_in[6];
    const float* ln_mlp_g = (const float*)d_in[7];
    const float* ln_mlp_b = (const float*)d_in[8];
    const float* Wq = (const float*)d_in[9];
    const float* bq = (const float*)d_in[10];
    const float* Wk = (const float*)d_in[11];
    const float* bk = (const float*)d_in[12];
    const float* Wv = (const float*)d_in[13];
    const float* bv = (const float*)d_in[14];
    const float* W_ih = (const float*)d_in[15];
    const float* b_ih = (const float*)d_in[16];
    const float* W_hh = (const float*)d_in[17];
    const float* b_hh = (const float*)d_in[18];
    const float* W1 = (const float*)d_in[19];
    const float* b1 = (const float*)d_in[20];
    const float* W2 = (const float*)d_in[21];
    const float* b2 = (const float*)d_in[22];
    float* out = (float*)d_out;

    float *p_hn, *p_m1, *p_slots, *p_Wqk, *p_wcomb;
    cudaGetSymbolAddress((void**)&p_hn, g_hn);
    cudaGetSymbolAddress((void**)&p_m1, g_m1);
    cudaGetSymbolAddress((void**)&p_slots, g_slots);
    cudaGetSymbolAddress((void**)&p_Wqk, g_Wqk);
    cudaGetSymbolAddress((void**)&p_wcomb, g_wcomb);

    // prep
    copy_slots_kernel<<<ROWS * Db / 256, 256>>>(slots);
    prep_micro_kernel<<<5, 256>>>(W_ih, b_ih, bv, Wq, bq, bk, Wk);
    // Wqk = Wq^T @ Wk  [256,256]
    gemm2_kernel<1, 0, 0><<<dim3(8, 4), 256>>>(Wq, Wk, nullptr, nullptr, p_Wqk, 256, 256, 256);
    // wcomb = W_ih @ Wv  [768,256]
    gemm2_kernel<0, 0, 0><<<dim3(24, 4), 256>>>(W_ih, Wv, nullptr, nullptr, p_wcomb, 768, 256, 256);

    for (int it = 0; it < 3; it++) {
        lnqk_kernel<<<NB, 256>>>(ln_slot_g, ln_slot_b);
        main_pass_kernel<<<NB * NBLK, 256>>>(inputs, ln_in_g, ln_in_b, it & 1);
        gigh_kernel<<<dim3(8, 12, 2), 256>>>(W_hh, b_hh);
        gru_ln_kernel<<<ROWS, 256>>>(ln_mlp_g, ln_mlp_b);
        // m1 = relu(hn @ W1^T + b1)  [256,512]
        gemm2_kernel<0, 1, 1><<<dim3(8, 8), 256>>>(p_hn, W1, b1, nullptr, p_m1, 256, 512, 256);
        // slots = m1 @ W2^T + b2 + slots  [256,256]
        float* Cdst = (it == 2) ? out : p_slots;
        gemm2_kernel<0, 1, 0><<<dim3(8, 4), 256>>>(p_m1, W2, b2, p_slots, Cdst, 256, 256, 512);
    }
}

// round 6
// speedup vs baseline: 1.2136x; 1.1299x over previous
#include <cuda_runtime.h>
#include <math.h>

#define Db 256
#define NB 32
#define NTOK 4096
#define NS 8
#define HMLP 512
#define NBLK 4
#define ROWS (NB * NS)
#define EPS_LN 1e-3f
#define EPS_ATTN 1e-8f
#define ATT_SCALE 0.0625f

// ---------------- static scratch ----------------
__device__ float g_slots[ROWS * Db];
__device__ float g_qk[ROWS * Db];
__device__ float g_qb[ROWS];
__device__ float g_partU[NB * NBLK * NS * Db];
__device__ float g_partZ[NB * NBLK * NS];
__device__ float g_gi[ROWS * 3 * Db];
__device__ float g_gh[ROWS * 3 * Db];
__device__ float g_hn[ROWS * Db];
__device__ float g_m1[ROWS * HMLP];
__device__ float g_Wqk[Db * Db];
__device__ float g_wcomb[3 * Db * Db];
__device__ float g_bcomb[3 * Db];
__device__ float g_wqbk[Db];
__device__ float g_bqk[Db];
__device__ float g_bqbk[1];

// ---------------- f32x2 packed helpers (sm_103a) ----------------
union F2U { float2 f; unsigned long long u; };
__device__ __forceinline__ float2 f2fma(float2 a, float2 b, float2 c) {
    F2U A, B, C, D;
    A.f = a; B.f = b; C.f = c;
    asm("fma.rn.f32x2 %0, %1, %2, %3;" : "=l"(D.u) : "l"(A.u), "l"(B.u), "l"(C.u));
    return D.f;
}
__device__ __forceinline__ float2 f2mul(float2 a, float2 b) {
    F2U A, B, D;
    A.f = a; B.f = b;
    asm("mul.rn.f32x2 %0, %1, %2;" : "=l"(D.u) : "l"(A.u), "l"(B.u));
    return D.f;
}
__device__ __forceinline__ float2 f2add(float2 a, float2 b) {
    F2U A, B, D;
    A.f = a; B.f = b;
    asm("add.rn.f32x2 %0, %1, %2;" : "=l"(D.u) : "l"(A.u), "l"(B.u));
    return D.f;
}

// ---------------- prep ----------------
__global__ void copy_slots_kernel(const float* __restrict__ slots) {
    int i = blockIdx.x * blockDim.x + threadIdx.x;
    g_slots[i] = slots[i];
}

__global__ void prep_micro_kernel(const float* __restrict__ W_ih, const float* __restrict__ b_ih,
                                  const float* __restrict__ bv, const float* __restrict__ Wq,
                                  const float* __restrict__ bq, const float* __restrict__ bk,
                                  const float* __restrict__ Wk) {
    int blk = blockIdx.x, t = threadIdx.x;
    if (blk < 3) {
        int o = blk * Db + t;
        float acc = b_ih[o];
        for (int d = 0; d < Db; d++) acc = fmaf(W_ih[o * Db + d], bv[d], acc);
        g_bcomb[o] = acc;
    } else if (blk == 3) {
        float acc = 0.f;
        for (int c = 0; c < Db; c++) acc = fmaf(Wq[c * Db + t], bk[c], acc);
        g_wqbk[t] = acc;
        __shared__ float red[Db];
        red[t] = bq[t] * bk[t];
        __syncthreads();
        for (int s = 128; s > 0; s >>= 1) {
            if (t < s) red[t] += red[t + s];
            __syncthreads();
        }
        if (t == 0) g_bqbk[0] = red[0];
    } else {
        float acc = 0.f;
        for (int c = 0; c < Db; c++) acc = fmaf(bq[c], Wk[c * Db + t], acc);
        g_bqk[t] = acc;
    }
}

// ---------------- ping-pong GEMM: 32x64 tile, K-step 32, double-buffered ----------------
// TRANSA: A is [K][R]. TRANSB: B is [O][K] (C=A@B^T), else [K][O].
// ASRC=1: A row r = (sum_c partU[b,c,s,:]) / (sum_c partZ[b,c,s]) -- the "u" finalize.
template <int TRANSA, int TRANSB, int RELU, int ASRC>
__global__ void __launch_bounds__(256, 2)
gemmp_kernel(const float* __restrict__ A, const float* __restrict__ Bm,
             const float* __restrict__ bias, const float* __restrict__ res,
             float* __restrict__ C, int R, int O, int K) {
    __shared__ float As[2][32][33];
    __shared__ float Bs[2][32][68];
    __shared__ float invZ[32];
    const int r0 = blockIdx.x * 32;
    const int o0 = blockIdx.y * 64;
    const int tid = threadIdx.x;
    const int tx = tid & 15;
    const int ty = tid >> 4;

    if (ASRC) {
        if (tid < 32) {
            int gr = r0 + tid, bi = gr >> 3, si = gr & 7;
            float zz = 0.f;
#pragma unroll
            for (int c = 0; c < NBLK; c++) zz += g_partZ[(bi * NBLK + c) * NS + si];
            invZ[tid] = 1.f / zz;
        }
        __syncthreads();
    }

    const int nk = K >> 5;
    float4 va, vb0, vb1;

    // stage loaders (kk = element offset in K)
#define LOAD_A(kk)                                                                        \
    do {                                                                                  \
        if (ASRC) {                                                                       \
            int r = tid >> 3;                                                             \
            int k4 = (tid & 7) << 2;                                                      \
            int gr = r0 + r, bi = gr >> 3, si = gr & 7;                                   \
            float4 s = *(const float4*)&g_partU[((bi * NBLK + 0) * NS + si) * Db + (kk) + k4]; \
            _Pragma("unroll") for (int c = 1; c < NBLK; c++) {                            \
                float4 vv = *(const float4*)&g_partU[((bi * NBLK + c) * NS + si) * Db + (kk) + k4]; \
                s.x += vv.x; s.y += vv.y; s.z += vv.z; s.w += vv.w;                       \
            }                                                                             \
            float iz = invZ[r];                                                           \
            va.x = s.x * iz; va.y = s.y * iz; va.z = s.z * iz; va.w = s.w * iz;           \
        } else if (TRANSA) {                                                              \
            int k = tid >> 3;                                                             \
            int r4 = (tid & 7) << 2;                                                      \
            va = *(const float4*)(A + (size_t)((kk) + k) * R + r0 + r4);                  \
        } else {                                                                          \
            int r = tid >> 3;                                                             \
            int k4 = (tid & 7) << 2;                                                      \
            va = *(const float4*)(A + (size_t)(r0 + r) * K + (kk) + k4);                  \
        }                                                                                 \
    } while (0)

#define LOAD_B(kk)                                                                        \
    do {                                                                                  \
        if (TRANSB) {                                                                     \
            int o = tid >> 2;                                                             \
            int k4 = (tid & 3) << 3;                                                      \
            vb0 = *(const float4*)(Bm + (size_t)(o0 + o) * K + (kk) + k4);                \
            vb1 = *(const float4*)(Bm + (size_t)(o0 + o) * K + (kk) + k4 + 4);            \
        } else {                                                                          \
            int k = tid >> 3;                                                             \
            int o8 = (tid & 7) << 3;                                                      \
            vb0 = *(const float4*)(Bm + (size_t)((kk) + k) * O + o0 + o8);                \
            vb1 = *(const float4*)(Bm + (size_t)((kk) + k) * O + o0 + o8 + 4);            \
        }                                                                                 \
    } while (0)

#define STORE_STAGE(buf)                                                                  \
    do {                                                                                  \
        if (TRANSA && !ASRC) {                                                            \
            int k = tid >> 3;                                                             \
            int r4 = (tid & 7) << 2;                                                      \
            As[buf][k][r4 + 0] = va.x; As[buf][k][r4 + 1] = va.y;                         \
            As[buf][k][r4 + 2] = va.z; As[buf][k][r4 + 3] = va.w;                         \
        } else {                                                                          \
            int r = tid >> 3;                                                             \
            int k4 = (tid & 7) << 2;                                                      \
            As[buf][k4 + 0][r] = va.x; As[buf][k4 + 1][r] = va.y;                         \
            As[buf][k4 + 2][r] = va.z; As[buf][k4 + 3][r] = va.w;                         \
        }                                                                                 \
        if (TRANSB) {                                                                     \
            int o = tid >> 2;                                                             \
            int k4 = (tid & 3) << 3;                                                      \
            Bs[buf][k4 + 0][o] = vb0.x; Bs[buf][k4 + 1][o] = vb0.y;                       \
            Bs[buf][k4 + 2][o] = vb0.z; Bs[buf][k4 + 3][o] = vb0.w;                       \
            Bs[buf][k4 + 4][o] = vb1.x; Bs[buf][k4 + 5][o] = vb1.y;                       \
            Bs[buf][k4 + 6][o] = vb1.z; Bs[buf][k4 + 7][o] = vb1.w;                       \
        } else {                                                                          \
            int k = tid >> 3;                                                             \
            int o8 = (tid & 7) << 3;                                                      \
            *(float4*)&Bs[buf][k][o8] = vb0;                                              \
            *(float4*)&Bs[buf][k][o8 + 4] = vb1;                                          \
        }                                                                                 \
    } while (0)

    float acc[2][4];
#pragma unroll
    for (int i = 0; i < 2; i++)
#pragma unroll
        for (int j = 0; j < 4; j++) acc[i][j] = 0.f;

    LOAD_A(0);
    LOAD_B(0);
    STORE_STAGE(0);
    __syncthreads();

    int cur = 0;
    for (int kki = 0; kki < nk; kki++) {
        if (kki + 1 < nk) {
            LOAD_A((kki + 1) << 5);
            LOAD_B((kki + 1) << 5);
        }
#pragma unroll
        for (int k = 0; k < 32; k++) {
            float a0 = As[cur][k][ty * 2 + 0];
            float a1 = As[cur][k][ty * 2 + 1];
            float4 b4 = *(const float4*)&Bs[cur][k][tx << 2];
            acc[0][0] = fmaf(a0, b4.x, acc[0][0]); acc[0][1] = fmaf(a0, b4.y, acc[0][1]);
            acc[0][2] = fmaf(a0, b4.z, acc[0][2]); acc[0][3] = fmaf(a0, b4.w, acc[0][3]);
            acc[1][0] = fmaf(a1, b4.x, acc[1][0]); acc[1][1] = fmaf(a1, b4.y, acc[1][1]);
            acc[1][2] = fmaf(a1, b4.z, acc[1][2]); acc[1][3] = fmaf(a1, b4.w, acc[1][3]);
        }
        if (kki + 1 < nk) STORE_STAGE(cur ^ 1);
        __syncthreads();
        cur ^= 1;
    }
#pragma unroll
    for (int i = 0; i < 2; i++) {
        int r = r0 + ty * 2 + i;
        float vv[4];
#pragma unroll
        for (int j = 0; j < 4; j++) {
            int o = o0 + (tx << 2) + j;
            float t = acc[i][j];
            if (bias) t += bias[o];
            if (RELU) t = fmaxf(t, 0.f);
            if (res) t += res[(size_t)r * O + o];
            vv[j] = t;
        }
        float4 v;
        v.x = vv[0]; v.y = vv[1]; v.z = vv[2]; v.w = vv[3];
        *(float4*)(C + (size_t)r * O + o0 + (tx << 2)) = v;
    }
#undef LOAD_A
#undef LOAD_B
#undef STORE_STAGE
}

// ---------------- fused slot LN + qb + qk GEMM (one block per batch) ----------------
__global__ void __launch_bounds__(256)
lnqk_kernel(const float* __restrict__ gpar, const float* __restrict__ bpar) {
    const int b = blockIdx.x;
    const int t = threadIdx.x;
    const int w = t >> 5, l = t & 31;
    __shared__ float sn[NS][Db];
    __shared__ float qbs[NS];

    const float4* sr = (const float4*)&g_slots[(b * NS + w) * Db];
    float4 a = sr[l * 2], c = sr[l * 2 + 1];
    float x[8] = {a.x, a.y, a.z, a.w, c.x, c.y, c.z, c.w};
    float s = 0.f, s2 = 0.f;
#pragma unroll
    for (int k = 0; k < 8; k++) {
        s += x[k];
        s2 = fmaf(x[k], x[k], s2);
    }
#pragma unroll
    for (int o = 16; o; o >>= 1) {
        s += __shfl_xor_sync(0xffffffffu, s, o);
        s2 += __shfl_xor_sync(0xffffffffu, s2, o);
    }
    float mean = s * (1.f / Db);
    float rstd = rsqrtf(s2 * (1.f / Db) - mean * mean + EPS_LN);
    float4 ga = ((const float4*)gpar)[l * 2], gc = ((const float4*)gpar)[l * 2 + 1];
    float4 ba = ((const float4*)bpar)[l * 2], bc = ((const float4*)bpar)[l * 2 + 1];
    float gg[8] = {ga.x, ga.y, ga.z, ga.w, gc.x, gc.y, gc.z, gc.w};
    float bb[8] = {ba.x, ba.y, ba.z, ba.w, bc.x, bc.y, bc.z, bc.w};
    float4 wa = ((const float4*)g_wqbk)[l * 2], wc = ((const float4*)g_wqbk)[l * 2 + 1];
    float wq[8] = {wa.x, wa.y, wa.z, wa.w, wc.x, wc.y, wc.z, wc.w};
    float p = 0.f;
#pragma unroll
    for (int k = 0; k < 8; k++) {
        float v = (x[k] - mean) * rstd * gg[k] + bb[k];
        sn[w][l * 8 + k] = v;
        p = fmaf(v, wq[k], p);
    }
#pragma unroll
    for (int o = 16; o; o >>= 1) p += __shfl_xor_sync(0xffffffffu, p, o);
    if (l == 0) qbs[w] = p + g_bqbk[0];
    __syncthreads();
    if (t < NS) g_qb[b * NS + t] = qbs[t];

    float acc[NS];
#pragma unroll
    for (int i = 0; i < NS; i++) acc[i] = g_bqk[t];
    for (int k = 0; k < Db; k += 4) {
        float w0 = g_Wqk[(k + 0) * Db + t];
        float w1 = g_Wqk[(k + 1) * Db + t];
        float w2 = g_Wqk[(k + 2) * Db + t];
        float w3 = g_Wqk[(k + 3) * Db + t];
#pragma unroll
        for (int i = 0; i < NS; i++) {
            float4 s4 = *(const float4*)&sn[i][k];
            acc[i] = fmaf(s4.x, w0, acc[i]);
            acc[i] = fmaf(s4.y, w1, acc[i]);
            acc[i] = fmaf(s4.z, w2, acc[i]);
            acc[i] = fmaf(s4.w, w3, acc[i]);
        }
    }
#pragma unroll
    for (int i = 0; i < NS; i++) g_qk[(b * NS + i) * Db + t] = acc[i];
}

// ---------------- main fused pass v2: f32x2 + prefetch ring ----------------
__global__ void __launch_bounds__(256, 1)
main_pass_kernel(const float* __restrict__ inputs, const float* __restrict__ ln_g,
                 const float* __restrict__ ln_b, int reverse) {
    const int batch = blockIdx.x / NBLK;
    const int chunk = blockIdx.x % NBLK;
    const int tid = threadIdx.x;
    const int w = tid >> 5, l = tid & 31;

    // scalar LN params for this lane's 8 elements
    float gg[8], bb[8];
    {
        float4 a = ((const float4*)ln_g)[l * 2];
        float4 c = ((const float4*)ln_g)[l * 2 + 1];
        gg[0] = a.x; gg[1] = a.y; gg[2] = a.z; gg[3] = a.w;
        gg[4] = c.x; gg[5] = c.y; gg[6] = c.z; gg[7] = c.w;
        float4 d = ((const float4*)ln_b)[l * 2];
        float4 e = ((const float4*)ln_b)[l * 2 + 1];
        bb[0] = d.x; bb[1] = d.y; bb[2] = d.z; bb[3] = d.w;
        bb[4] = e.x; bb[5] = e.y; bb[6] = e.z; bb[7] = e.w;
    }
    float2 g2[4], b2[4];
#pragma unroll
    for (int k = 0; k < 4; k++) {
        g2[k] = make_float2(gg[2 * k], gg[2 * k + 1]);
        b2[k] = make_float2(bb[2 * k], bb[2 * k + 1]);
    }

    // qkg2 = qk * g * SCALE (packed, per-lane-element); A_ = SCALE*(qk.g); Bc = SCALE*(qk.b + qb)
    float2 qkg2[NS][4];
    float A_[NS], Bc[NS];
    {
        const float4* qkb = (const float4*)&g_qk[batch * NS * Db];
#pragma unroll
        for (int i = 0; i < NS; i++) {
            float4 a = qkb[i * 64 + l * 2];
            float4 c = qkb[i * 64 + l * 2 + 1];
            float qk[8] = {a.x, a.y, a.z, a.w, c.x, c.y, c.z, c.w};
            float aL = 0.f, bL = 0.f;
#pragma unroll
            for (int k = 0; k < 8; k++) {
                aL = fmaf(qk[k], gg[k], aL);
                bL = fmaf(qk[k], bb[k], bL);
            }
#pragma unroll
            for (int k = 0; k < 4; k++)
                qkg2[i][k] = make_float2(qk[2 * k] * gg[2 * k] * ATT_SCALE,
                                         qk[2 * k + 1] * gg[2 * k + 1] * ATT_SCALE);
            A_[i] = aL;
            Bc[i] = bL;
        }
#pragma unroll
        for (int o = 16; o; o >>= 1) {
#pragma unroll
            for (int i = 0; i < NS; i++) {
                A_[i] += __shfl_xor_sync(0xffffffffu, A_[i], o);
                Bc[i] += __shfl_xor_sync(0xffffffffu, Bc[i], o);
            }
        }
#pragma unroll
        for (int i = 0; i < NS; i++) {
            A_[i] *= ATT_SCALE;
            Bc[i] = (Bc[i] + g_qb[batch * NS + i]) * ATT_SCALE;
        }
    }

    float2 U2[NS][4];
    float Z[NS];
#pragma unroll
    for (int i = 0; i < NS; i++) {
        Z[i] = 0.f;
#pragma unroll
        for (int k = 0; k < 4; k++) U2[i][k] = make_float2(0.f, 0.f);
    }

    const int TPW = NTOK / NBLK / 8;  // 128 tokens per warp
    const int base = chunk * (NTOK / NBLK) + w * TPW;

    float4 rga[4], rgc[4];
#pragma unroll
    for (int j = 0; j < 3; j++) {
        int tok = reverse ? (base + TPW - 1 - j) : (base + j);
        const float4* xp = (const float4*)&inputs[(size_t)(batch * NTOK + tok) * Db];
        rga[j] = xp[l * 2];
        rgc[j] = xp[l * 2 + 1];
    }

#pragma unroll 1
    for (int tt = 0; tt < TPW; tt += 4) {
#pragma unroll
        for (int j = 0; j < 4; j++) {
            int ft = tt + j + 3;
            if (ft < TPW) {
                int tok = reverse ? (base + TPW - 1 - ft) : (base + ft);
                const float4* xp = (const float4*)&inputs[(size_t)(batch * NTOK + tok) * Db];
                rga[(j + 3) & 3] = xp[l * 2];
                rgc[(j + 3) & 3] = xp[l * 2 + 1];
            }
            float2 x2[4];
            x2[0] = make_float2(rga[j].x, rga[j].y);
            x2[1] = make_float2(rga[j].z, rga[j].w);
            x2[2] = make_float2(rgc[j].x, rgc[j].y);
            x2[3] = make_float2(rgc[j].z, rgc[j].w);

            // packed partials: (s, s2) and 8 dot partials on raw x
            float2 sv = make_float2(0.f, 0.f);
            float2 qv = make_float2(0.f, 0.f);
            float2 pd2[NS];
#pragma unroll
            for (int i = 0; i < NS; i++) pd2[i] = make_float2(0.f, 0.f);
#pragma unroll
            for (int k = 0; k < 4; k++) {
                sv = f2add(sv, x2[k]);
                qv = f2fma(x2[k], x2[k], qv);
#pragma unroll
                for (int i = 0; i < NS; i++) pd2[i] = f2fma(qkg2[i][k], x2[k], pd2[i]);
            }
            float s = sv.x + sv.y;
            float s2 = qv.x + qv.y;
            float d[NS];
#pragma unroll
            for (int i = 0; i < NS; i++) d[i] = pd2[i].x + pd2[i].y;
            // single fused butterfly (10 values)
#pragma unroll
            for (int o = 16; o; o >>= 1) {
                s += __shfl_xor_sync(0xffffffffu, s, o);
                s2 += __shfl_xor_sync(0xffffffffu, s2, o);
#pragma unroll
                for (int i = 0; i < NS; i++) d[i] += __shfl_xor_sync(0xffffffffu, d[i], o);
            }
            float mean = s * (1.f / Db);
            float rstd = rsqrtf(s2 * (1.f / Db) - mean * mean + EPS_LN);
            float mr = -mean * rstd;
            // d_i = rstd*pd + mr*A_ + Bc  (all pre-scaled by ATT_SCALE)
            float mx = -1e30f;
#pragma unroll
            for (int i = 0; i < NS; i++) {
                d[i] = fmaf(rstd, d[i], fmaf(mr, A_[i], Bc[i]));
                mx = fmaxf(mx, d[i]);
            }
            float p[NS], se = 0.f;
#pragma unroll
            for (int i = 0; i < NS; i++) {
                p[i] = __expf(d[i] - mx);
                se += p[i];
            }
            float inv = __fdividef(1.f, se);
            // xn = x*(rstd*g) + (b - mean*rstd*g)
            float2 rstd2 = make_float2(rstd, rstd);
            float2 nm2 = make_float2(mr, mr);  // -mean*rstd
            float2 xn2[4];
#pragma unroll
            for (int k = 0; k < 4; k++) {
                float2 w2 = f2mul(g2[k], rstd2);
                float2 c2 = f2fma(nm2, g2[k], b2[k]);  // b - mean*rstd*g
                xn2[k] = f2fma(x2[k], w2, c2);
            }
#pragma unroll
            for (int i = 0; i < NS; i++) {
                float pi = fmaf(p[i], inv, EPS_ATTN);
                Z[i] += pi;
                float2 pp = make_float2(pi, pi);
#pragma unroll
                for (int k = 0; k < 4; k++) U2[i][k] = f2fma(pp, xn2[k], U2[i][k]);
            }
        }
    }

    // serial cross-warp reduction (deterministic)
    __shared__ float sU[NS * Db];
    __shared__ float sZ[NS];
    for (int ww = 0; ww < 8; ww++) {
        if (w == ww) {
#pragma unroll
            for (int i = 0; i < NS; i++) {
#pragma unroll
                for (int k = 0; k < 4; k++) {
                    int idx = i * Db + l * 8 + 2 * k;
                    if (ww == 0) {
                        sU[idx] = U2[i][k].x;
                        sU[idx + 1] = U2[i][k].y;
                    } else {
                        sU[idx] += U2[i][k].x;
                        sU[idx + 1] += U2[i][k].y;
                    }
                }
            }
            if (l == 0) {
#pragma unroll
                for (int i = 0; i < NS; i++) {
                    if (ww == 0) sZ[i] = Z[i];
                    else sZ[i] += Z[i];
                }
            }
        }
        __syncthreads();
    }
    int outb = (batch * NBLK + chunk) * NS * Db;
    for (int idx = tid; idx < NS * Db; idx += 256) g_partU[outb + idx] = sU[idx];
    if (tid < NS) g_partZ[(batch * NBLK + chunk) * NS + tid] = sZ[tid];
}

// ---------------- GRU elementwise + LN(mlp) fused ----------------
__global__ void gru_ln_kernel(const float* __restrict__ g, const float* __restrict__ bpar) {
    int row = blockIdx.x;
    int t = threadIdx.x;
    int w = t >> 5, l = t & 31;
    const float* gi = &g_gi[row * 3 * Db];
    const float* gh = &g_gh[row * 3 * Db];
    float h = g_slots[row * Db + t];
    float r = 1.f / (1.f + expf(-(gi[t] + gh[t])));
    float z = 1.f / (1.f + expf(-(gi[Db + t] + gh[Db + t])));
    float n = tanhf(gi[2 * Db + t] + r * gh[2 * Db + t]);
    float hn = (1.f - z) * n + z * h;
    g_slots[row * Db + t] = hn;
    __shared__ float sm[8], sm2[8], bc[2];
    float s = hn, s2 = hn * hn;
#pragma unroll
    for (int o = 16; o; o >>= 1) {
        s += __shfl_xor_sync(0xffffffffu, s, o);
        s2 += __shfl_xor_sync(0xffffffffu, s2, o);
    }
    if (l == 0) { sm[w] = s; sm2[w] = s2; }
    __syncthreads();
    if (t == 0) {
        float a = 0.f, a2 = 0.f;
#pragma unroll
        for (int i = 0; i < 8; i++) { a += sm[i]; a2 += sm2[i]; }
        float m = a * (1.f / Db);
        bc[0] = m;
        bc[1] = rsqrtf(a2 * (1.f / Db) - m * m + EPS_LN);
    }
    __syncthreads();
    g_hn[row * Db + t] = (hn - bc[0]) * bc[1] * g[t] + bpar[t];
}

// ---------------- launch ----------------
extern "C" void kernel_launch(void* const* d_in, const int* in_sizes, int n_in,
                              void* d_out, int out_size) {
    const float* inputs = (const float*)d_in[0];
    const float* slots = (const float*)d_in[1];
    const float* ln_in_g = (const float*)d_in[3];
    const float* ln_in_b = (const float*)d_in[4];
    const float* ln_slot_g = (const float*)d_in[5];
    const float* ln_slot_b = (const float*)d_in[6];
    const float* ln_mlp_g = (const float*)d_in[7];
    const float* ln_mlp_b = (const float*)d_in[8];
    const float* Wq = (const float*)d_in[9];
    const float* bq = (const float*)d_in[10];
    const float* Wk = (const float*)d_in[11];
    const float* bk = (const float*)d_in[12];
    const float* Wv = (const float*)d_in[13];
    const float* bv = (const float*)d_in[14];
    const float* W_ih = (const float*)d_in[15];
    const float* b_ih = (const float*)d_in[16];
    const float* W_hh = (const float*)d_in[17];
    const float* b_hh = (const float*)d_in[18];
    const float* W1 = (const float*)d_in[19];
    const float* b1 = (const float*)d_in[20];
    const float* W2 = (const float*)d_in[21];
    const float* b2 = (const float*)d_in[22];
    float* out = (float*)d_out;

    float *p_hn, *p_m1, *p_slots, *p_Wqk, *p_wcomb, *p_gi, *p_gh, *p_bcomb;
    cudaGetSymbolAddress((void**)&p_hn, g_hn);
    cudaGetSymbolAddress((void**)&p_m1, g_m1);
    cudaGetSymbolAddress((void**)&p_slots, g_slots);
    cudaGetSymbolAddress((void**)&p_Wqk, g_Wqk);
    cudaGetSymbolAddress((void**)&p_wcomb, g_wcomb);
    cudaGetSymbolAddress((void**)&p_gi, g_gi);
    cudaGetSymbolAddress((void**)&p_gh, g_gh);
    cudaGetSymbolAddress((void**)&p_bcomb, g_bcomb);

    // prep
    copy_slots_kernel<<<ROWS * Db / 256, 256>>>(slots);
    prep_micro_kernel<<<5, 256>>>(W_ih, b_ih, bv, Wq, bq, bk, Wk);
    // Wqk = Wq^T @ Wk  [256,256]
    gemmp_kernel<1, 0, 0, 0><<<dim3(8, 4), 256>>>(Wq, Wk, nullptr, nullptr, p_Wqk, 256, 256, 256);
    // wcomb = W_ih @ Wv  [768,256]
    gemmp_kernel<0, 0, 0, 0><<<dim3(24, 4), 256>>>(W_ih, Wv, nullptr, nullptr, p_wcomb, 768, 256, 256);

    for (int it = 0; it < 3; it++) {
        lnqk_kernel<<<NB, 256>>>(ln_slot_g, ln_slot_b);
        main_pass_kernel<<<NB * NBLK, 256>>>(inputs, ln_in_g, ln_in_b, it & 1);
        // gi = u @ wcomb^T + bcomb   (u finalized from partU/partZ inside A-stage)
        gemmp_kernel<0, 1, 0, 1><<<dim3(8, 12), 256>>>(nullptr, p_wcomb, p_bcomb, nullptr, p_gi, 256, 768, 256);
        // gh = slots @ W_hh^T + b_hh
        gemmp_kernel<0, 1, 0, 0><<<dim3(8, 12), 256>>>(p_slots, W_hh, b_hh, nullptr, p_gh, 256, 768, 256);
        gru_ln_kernel<<<ROWS, 256>>>(ln_mlp_g, ln_mlp_b);
        // m1 = relu(hn @ W1^T + b1)
        gemmp_kernel<0, 1, 1, 0><<<dim3(8, 8), 256>>>(p_hn, W1, b1, nullptr, p_m1, 256, 512, 256);
        // slots = m1 @ W2^T + b2 + slots
        float* Cdst = (it == 2) ? out : p_slots;
        gemmp_kernel<0, 1, 0, 0><<<dim3(8, 4), 256>>>(p_m1, W2, b2, p_slots, Cdst, 256, 256, 512);
    }
}